// round 5
// baseline (speedup 1.0000x reference)
#include <cuda_runtime.h>

#define WIN  48
#define HALO 47
#define BK   256
#define WPB  256              // outputs per block (CH=1)
#define NB   (WPB + HALO)     // 303 betas per block
#define TX   (NB + HALO)      // 350 x rows staged per block
#define RX   2                // 2*256 = 512 >= TX+1
#define RB   2                // 512 >= NB+1
#define XOFF 0.75f            // centering constant (exact algebra for any value)

// ---- shared layout ----
// [ s_mp0 float4*(TX+1) | s_mp1 float4*(TX+1) | s_mp2 float*(TX+1) ]  (12640 B)
//   s_bp (float4*(NB+1) = 4864 B) aliases s_mp0 after the beta stage.
// [ s_raw float*(3*TX) ] (4200 B)   [ s_wt 8*9 floats ] (288 B)
#define U2_BYTES ((2 * (TX + 1) * 16 + (TX + 1) * 4 + 15) & ~15)
#define WT_OFF   (U2_BYTES + 3 * TX * 4)
#define SMEM_TOT (WT_OFF + 8 * 9 * 4)

// Block-wide exclusive scan of NCH register channels. wt >= 8*NCH floats.
template<int NCH>
__device__ __forceinline__ void block_scan_excl(float (&v)[NCH], float* wt, int t) {
    const int lane = t & 31, w = t >> 5;
    float inc[NCH];
#pragma unroll
    for (int c = 0; c < NCH; ++c) inc[c] = v[c];
#pragma unroll
    for (int d = 1; d < 32; d <<= 1) {
#pragma unroll
        for (int c = 0; c < NCH; ++c) {
            const float u = __shfl_up_sync(0xffffffffu, inc[c], d);
            if (lane >= d) inc[c] += u;
        }
    }
    if (lane == 31) {
#pragma unroll
        for (int c = 0; c < NCH; ++c) wt[w * NCH + c] = inc[c];
    }
    __syncthreads();
    if (t < 8) {   // 8 warp totals
        float s[NCH];
#pragma unroll
        for (int c = 0; c < NCH; ++c) s[c] = wt[t * NCH + c];
#pragma unroll
        for (int d = 1; d < 8; d <<= 1) {
#pragma unroll
            for (int c = 0; c < NCH; ++c) {
                const float u = __shfl_up_sync(0x000000ffu, s[c], d);
                if (t >= d) s[c] += u;
            }
        }
#pragma unroll
        for (int c = 0; c < NCH; ++c) wt[t * NCH + c] = s[c];
    }
    __syncthreads();
#pragma unroll
    for (int c = 0; c < NCH; ++c) {
        const float base = (w > 0) ? wt[(w - 1) * NCH + c] : 0.f;
        v[c] = base + inc[c] - v[c];   // exclusive prefix at this thread's chunk start
    }
}

__global__ __launch_bounds__(BK, 6) void pos_fused_kernel(const float* __restrict__ x,
                                                          const float* __restrict__ Wm,
                                                          float* __restrict__ H,
                                                          int N, int K) {
    __shared__ __align__(16) char smem[SMEM_TOT];
    float4* s_mp0 = (float4*)smem;                       // {Sx,Sy,Sz,Mxx} prefix
    float4* s_mp1 = s_mp0 + (TX + 1);                    // {Myy,Mzz,Mxy,Mxz}
    float*  s_mp2 = (float*)(s_mp1 + (TX + 1));          // Myz
    float4* s_bp  = (float4*)smem;                       // beta prefix (aliases s_mp0)
    float*  s_raw = (float*)(smem + U2_BYTES);           // centered x, AoS [3*TX]
    float*  s_wt  = (float*)(smem + WT_OFF);

    const int t  = threadIdx.x;
    const int n0 = blockIdx.x * WPB;
    const int kb = n0 - HALO;                            // global row of local index 0
    const int g0 = 3 * kb;

    // --- stage raw x (centered), coalesced; pad = 0 ---
    for (int e = t; e < 3 * TX; e += BK) {
        const int g = g0 + e;
        s_raw[e] = (g >= 0 && g < 3 * N) ? (x[g] - XOFF) : 0.f;
    }
    __syncthreads();

    // --- extract this thread's output x row now (s_raw stable until scan1 done) ---
    float oxr, oxg, oxb;
    {
        const int j = t + HALO;   // local row of output m = t
        oxr = s_raw[3 * j]     + XOFF;
        oxg = s_raw[3 * j + 1] + XOFF;
        oxb = s_raw[3 * j + 2] + XOFF;
    }

    // --- scan 9 moment channels over TX rows ---
    {
        float v[9];
#pragma unroll
        for (int c = 0; c < 9; ++c) v[c] = 0.f;
#pragma unroll
        for (int r = 0; r < RX; ++r) {
            const int i = t * RX + r;
            if (i < TX) {
                const float X = s_raw[3 * i], Y = s_raw[3 * i + 1], Z = s_raw[3 * i + 2];
                v[0] += X; v[1] += Y; v[2] += Z;
                v[3] = fmaf(X, X, v[3]); v[4] = fmaf(Y, Y, v[4]); v[5] = fmaf(Z, Z, v[5]);
                v[6] = fmaf(X, Y, v[6]); v[7] = fmaf(X, Z, v[7]); v[8] = fmaf(Y, Z, v[8]);
            }
        }
        block_scan_excl<9>(v, s_wt, t);
#pragma unroll
        for (int r = 0; r < RX; ++r) {
            const int i = t * RX + r;
            if (i <= TX) {
                s_mp0[i] = make_float4(v[0], v[1], v[2], v[3]);
                s_mp1[i] = make_float4(v[4], v[5], v[6], v[7]);
                s_mp2[i] = v[8];
                if (i < TX) {
                    const float X = s_raw[3 * i], Y = s_raw[3 * i + 1], Z = s_raw[3 * i + 2];
                    v[0] += X; v[1] += Y; v[2] += Z;
                    v[3] = fmaf(X, X, v[3]); v[4] = fmaf(Y, Y, v[4]); v[5] = fmaf(Z, Z, v[5]);
                    v[6] = fmaf(X, Y, v[6]); v[7] = fmaf(X, Z, v[7]); v[8] = fmaf(Y, Z, v[8]);
                }
            }
        }
    }
    __syncthreads();

    // --- betas computed at scan-2 chunk indices, kept in registers through the scan ---
    const float W00 = Wm[0], W01 = Wm[1], W02 = Wm[2];
    const float W10 = Wm[3], W11 = Wm[4], W12 = Wm[5];
    const float r0 = W00 + W01 + W02;
    const float r1 = W10 + W11 + W12;

    float4 vb[RB];
    float v4[4] = {0.f, 0.f, 0.f, 0.f};
#pragma unroll
    for (int r = 0; r < RB; ++r) {
        const int i = t * RB + r;
        float4 out = make_float4(0.f, 0.f, 0.f, 0.f);
        if (i < NB) {
            const int k = kb + i;
            if (k >= 0 && k < K) {
                const float4 a0 = s_mp0[i], a1 = s_mp0[i + WIN];
                const float4 b0 = s_mp1[i], b1 = s_mp1[i + WIN];
                const float Sx  = a1.x - a0.x, Sy  = a1.y - a0.y, Sz  = a1.z - a0.z;
                const float Mxx = a1.w - a0.w;
                const float Myy = b1.x - b0.x, Mzz = b1.y - b0.y;
                const float Mxy = b1.z - b0.z, Mxz = b1.w - b0.w;
                const float Myz = s_mp2[i + WIN] - s_mp2[i];

                const float imr = __fdividef(48.f, Sx + 48.f * XOFF);
                const float img = __fdividef(48.f, Sy + 48.f * XOFF);
                const float imb = __fdividef(48.f, Sz + 48.f * XOFF);
                const float a0r = W00 * imr, a0g = W01 * img, a0b = W02 * imb;
                const float a1r = W10 * imr, a1g = W11 * img, a1b = W12 * imb;
                const float T0 = a0r * Sx + a0g * Sy + a0b * Sz;
                const float T1 = a1r * Sx + a1g * Sy + a1b * Sz;
                const float q0 = a0r * a0r * Mxx + a0g * a0g * Myy + a0b * a0b * Mzz
                               + 2.f * (a0r * a0g * Mxy + a0r * a0b * Mxz + a0g * a0b * Myz)
                               - T0 * T0 * (1.f / 48.f);
                const float q1 = a1r * a1r * Mxx + a1g * a1g * Myy + a1b * a1b * Mzz
                               + 2.f * (a1r * a1g * Mxy + a1r * a1b * Mxz + a1g * a1b * Myz)
                               - T1 * T1 * (1.f / 48.f);
                const float alpha = q0 * rsqrtf(q0 * q1);   // sqrt(q0/q1)
                out.x = fmaf(alpha, W10, W00) * imr;
                out.y = fmaf(alpha, W11, W01) * img;
                out.z = fmaf(alpha, W12, W02) * imb;
                out.w = fmaf(alpha, r1, r0);                // beta . m (exact)
            }
        }
        vb[r] = out;
        v4[0] += out.x; v4[1] += out.y; v4[2] += out.z; v4[3] += out.w;
    }

    // scan's first internal barrier also fences the s_mp0 reads above,
    // so pass-2 may safely overwrite s_mp0 with the beta prefix.
    block_scan_excl<4>(v4, s_wt, t);
#pragma unroll
    for (int r = 0; r < RB; ++r) {
        const int i = t * RB + r;
        if (i <= NB) {
            s_bp[i] = make_float4(v4[0], v4[1], v4[2], v4[3]);
            v4[0] += vb[r].x; v4[1] += vb[r].y; v4[2] += vb[r].z; v4[3] += vb[r].w;
        }
    }
    __syncthreads();

    // --- output: H[n] = x[n] . slidingSum(beta) - slidingSum(gamma) ---
    {
        const int n = n0 + t;
        if (n < N) {
            const float4 p0 = s_bp[t], p1 = s_bp[t + WIN];
            const float Br = p1.x - p0.x;
            const float Bg = p1.y - p0.y;
            const float Bb = p1.z - p0.z;
            const float G  = p1.w - p0.w;
            H[n] = fmaf(oxr, Br, fmaf(oxg, Bg, fmaf(oxb, Bb, -G)));
        }
    }
}

extern "C" void kernel_launch(void* const* d_in, const int* in_sizes, int n_in,
                              void* d_out, int out_size) {
    const float* x  = (const float*)d_in[0];   // rgbs [1, N, 3]
    const float* Wm = (const float*)d_in[1];   // W [2,3]
    // d_in[2] = bias: cancels exactly (h is window-mean-centered).

    const int N = in_sizes[0] / 3;
    const int K = N - WIN;
    float* H = (float*)d_out;

    const int grid = (N + WPB - 1) / WPB;
    pos_fused_kernel<<<grid, BK>>>(x, Wm, H, N, K);
}

// round 6
// speedup vs baseline: 1.2948x; 1.2948x over previous
#include <cuda_runtime.h>

#define WIN  48
#define HALO 47
#define BK   256
#define CH   4
#define WPB  (BK * CH)        // 1024 outputs per block
#define NB   (WPB + HALO)     // 1071 betas per block
#define TX   (NB + HALO)      // 1118 x rows staged per block
#define RX   5                // 5*256 = 1280 >= TX+1
#define RB   5                // 1280 >= NB+1
#define XOFF 0.75f            // centering constant (exact algebra)

// ---- shared layout ----
// [ s_mp0 float4*(TX+1) | s_mp1 float4*(TX+1) | s_mp2 float*(TX+1) ]
//   s_bp (float4*(NB+1)) aliases s_mp0 after the beta stage.
// [ s_raw float*(3*TX) ]  [ s_wt 8*9 floats ]
#define U2_BYTES ((2 * (TX + 1) * 16 + (TX + 1) * 4 + 15) & ~15)
#define WT_OFF   (U2_BYTES + 3 * TX * 4)
#define SMEM_TOT (WT_OFF + 8 * 9 * 4)

// Warp-level pieces of the block scan. Second level is done redundantly by
// every warp (lanes 0..7 scan the 8 warp totals), removing a barrier and the
// single-warp serialization.
template<int NCH>
__device__ __forceinline__ void warp_incl_scan(float (&v)[NCH], int lane) {
#pragma unroll
    for (int d = 1; d < 32; d <<= 1) {
#pragma unroll
        for (int c = 0; c < NCH; ++c) {
            const float u = __shfl_up_sync(0xffffffffu, v[c], d);
            if (lane >= d) v[c] += u;
        }
    }
}

__global__ __launch_bounds__(BK) void pos_fused_kernel(const float* __restrict__ x,
                                                       const float* __restrict__ Wm,
                                                       float* __restrict__ H,
                                                       int N, int K) {
    __shared__ __align__(16) char smem[SMEM_TOT];
    float4* s_mp0 = (float4*)smem;                       // {Sx,Sy,Sz,Mxx} prefix
    float4* s_mp1 = s_mp0 + (TX + 1);                    // {Myy,Mzz,Mxy,Mxz}
    float*  s_mp2 = (float*)(s_mp1 + (TX + 1));          // Myz
    float4* s_bp  = (float4*)smem;                       // beta prefix (aliases s_mp0)
    float*  s_raw = (float*)(smem + U2_BYTES);           // centered x, AoS [3*TX]
    float*  s_wt  = (float*)(smem + WT_OFF);

    const int t    = threadIdx.x;
    const int lane = t & 31, w = t >> 5;
    const int n0 = blockIdx.x * WPB;
    const int kb = n0 - HALO;                            // global row of local index 0
    const int g0 = 3 * kb;

    // --- stage raw x (centered), coalesced; pad = 0 ---
    for (int e = t; e < 3 * TX; e += BK) {
        const int g = g0 + e;
        s_raw[e] = (g >= 0 && g < 3 * N) ? (x[g] - XOFF) : 0.f;
    }
    __syncthreads();                                                // B1

    // ================== scan 9 moment channels over TX rows ==================
    {
        float v[9];
#pragma unroll
        for (int c = 0; c < 9; ++c) v[c] = 0.f;
#pragma unroll
        for (int r = 0; r < RX; ++r) {
            const int i = t * RX + r;
            if (i < TX) {
                const float X = s_raw[3 * i], Y = s_raw[3 * i + 1], Z = s_raw[3 * i + 2];
                v[0] += X; v[1] += Y; v[2] += Z;
                v[3] = fmaf(X, X, v[3]); v[4] = fmaf(Y, Y, v[4]); v[5] = fmaf(Z, Z, v[5]);
                v[6] = fmaf(X, Y, v[6]); v[7] = fmaf(X, Z, v[7]); v[8] = fmaf(Y, Z, v[8]);
            }
        }
        float tot[9];
#pragma unroll
        for (int c = 0; c < 9; ++c) tot[c] = v[c];
        warp_incl_scan<9>(tot, lane);           // inclusive over thread chunks
        if (lane == 31) {
#pragma unroll
            for (int c = 0; c < 9; ++c) s_wt[w * 9 + c] = tot[c];
        }
        __syncthreads();                                            // B2
        // redundant 2nd level: lanes 0..7 scan the 8 warp totals
        float wtot[9];
#pragma unroll
        for (int c = 0; c < 9; ++c) wtot[c] = (lane < 8) ? s_wt[lane * 9 + c] : 0.f;
#pragma unroll
        for (int d = 1; d < 8; d <<= 1) {
#pragma unroll
            for (int c = 0; c < 9; ++c) {
                const float u = __shfl_up_sync(0xffffffffu, wtot[c], d);
                if (lane >= d) wtot[c] += u;
            }
        }
#pragma unroll
        for (int c = 0; c < 9; ++c) {
            const float wb = __shfl_sync(0xffffffffu, wtot[c], (w > 0) ? (w - 1) : 0);
            v[c] = ((w > 0) ? wb : 0.f) + (tot[c] - v[c]);   // exclusive prefix at chunk start
        }
        // pass 2: emit prefixes
#pragma unroll
        for (int r = 0; r < RX; ++r) {
            const int i = t * RX + r;
            if (i <= TX) {
                s_mp0[i] = make_float4(v[0], v[1], v[2], v[3]);
                s_mp1[i] = make_float4(v[4], v[5], v[6], v[7]);
                s_mp2[i] = v[8];
                if (i < TX) {
                    const float X = s_raw[3 * i], Y = s_raw[3 * i + 1], Z = s_raw[3 * i + 2];
                    v[0] += X; v[1] += Y; v[2] += Z;
                    v[3] = fmaf(X, X, v[3]); v[4] = fmaf(Y, Y, v[4]); v[5] = fmaf(Z, Z, v[5]);
                    v[6] = fmaf(X, Y, v[6]); v[7] = fmaf(X, Z, v[7]); v[8] = fmaf(Y, Z, v[8]);
                }
            }
        }
    }
    __syncthreads();                                                // B3

    // ====== betas at scan-2 chunk indices, held in registers through scan-2 ======
    const float W00 = Wm[0], W01 = Wm[1], W02 = Wm[2];
    const float W10 = Wm[3], W11 = Wm[4], W12 = Wm[5];
    const float r0 = W00 + W01 + W02;
    const float r1 = W10 + W11 + W12;

    float4 vb[RB];
    float v4[4] = {0.f, 0.f, 0.f, 0.f};
#pragma unroll
    for (int r = 0; r < RB; ++r) {
        const int i = t * RB + r;
        float4 out = make_float4(0.f, 0.f, 0.f, 0.f);
        if (i < NB) {
            const int k = kb + i;
            if (k >= 0 && k < K) {
                const float4 a0 = s_mp0[i], a1 = s_mp0[i + WIN];
                const float4 b0 = s_mp1[i], b1 = s_mp1[i + WIN];
                const float Sx  = a1.x - a0.x, Sy  = a1.y - a0.y, Sz  = a1.z - a0.z;
                const float Mxx = a1.w - a0.w;
                const float Myy = b1.x - b0.x, Mzz = b1.y - b0.y;
                const float Mxy = b1.z - b0.z, Mxz = b1.w - b0.w;
                const float Myz = s_mp2[i + WIN] - s_mp2[i];

                const float imr = __fdividef(48.f, Sx + 48.f * XOFF);
                const float img = __fdividef(48.f, Sy + 48.f * XOFF);
                const float imb = __fdividef(48.f, Sz + 48.f * XOFF);
                const float a0r = W00 * imr, a0g = W01 * img, a0b = W02 * imb;
                const float a1r = W10 * imr, a1g = W11 * img, a1b = W12 * imb;
                const float T0 = a0r * Sx + a0g * Sy + a0b * Sz;
                const float T1 = a1r * Sx + a1g * Sy + a1b * Sz;
                const float q0 = a0r * a0r * Mxx + a0g * a0g * Myy + a0b * a0b * Mzz
                               + 2.f * (a0r * a0g * Mxy + a0r * a0b * Mxz + a0g * a0b * Myz)
                               - T0 * T0 * (1.f / 48.f);
                const float q1 = a1r * a1r * Mxx + a1g * a1g * Myy + a1b * a1b * Mzz
                               + 2.f * (a1r * a1g * Mxy + a1r * a1b * Mxz + a1g * a1b * Myz)
                               - T1 * T1 * (1.f / 48.f);
                const float alpha = q0 * rsqrtf(q0 * q1);   // sqrt(q0/q1)
                out.x = fmaf(alpha, W10, W00) * imr;
                out.y = fmaf(alpha, W11, W01) * img;
                out.z = fmaf(alpha, W12, W02) * imb;
                out.w = fmaf(alpha, r1, r0);                // beta . m (exact)
            }
        }
        vb[r] = out;
        v4[0] += out.x; v4[1] += out.y; v4[2] += out.z; v4[3] += out.w;
    }

    // ================== scan 4 beta channels ==================
    {
        float tot[4];
#pragma unroll
        for (int c = 0; c < 4; ++c) tot[c] = v4[c];
        warp_incl_scan<4>(tot, lane);
        if (lane == 31) {
#pragma unroll
            for (int c = 0; c < 4; ++c) s_wt[w * 4 + c] = tot[c];
        }
        __syncthreads();   // B4: also fences all s_mp0 reads before s_bp overwrite
        float wtot[4];
#pragma unroll
        for (int c = 0; c < 4; ++c) wtot[c] = (lane < 8) ? s_wt[lane * 4 + c] : 0.f;
#pragma unroll
        for (int d = 1; d < 8; d <<= 1) {
#pragma unroll
            for (int c = 0; c < 4; ++c) {
                const float u = __shfl_up_sync(0xffffffffu, wtot[c], d);
                if (lane >= d) wtot[c] += u;
            }
        }
#pragma unroll
        for (int c = 0; c < 4; ++c) {
            const float wb = __shfl_sync(0xffffffffu, wtot[c], (w > 0) ? (w - 1) : 0);
            v4[c] = ((w > 0) ? wb : 0.f) + (tot[c] - v4[c]);
        }
#pragma unroll
        for (int r = 0; r < RB; ++r) {
            const int i = t * RB + r;
            if (i <= NB) {
                s_bp[i] = make_float4(v4[0], v4[1], v4[2], v4[3]);
                v4[0] += vb[r].x; v4[1] += vb[r].y; v4[2] += vb[r].z; v4[3] += vb[r].w;
            }
        }
    }
    __syncthreads();                                                // B5

    // ====== outputs: H[n] = x[n] . slidingSum(beta) - slidingSum(gamma) ======
#pragma unroll
    for (int c0 = 0; c0 < CH; ++c0) {
        const int m = t + c0 * BK;
        const int n = n0 + m;
        if (n < N) {
            const float4 p0 = s_bp[m], p1 = s_bp[m + WIN];
            const int j = 3 * (m + HALO);
            const float xr = s_raw[j]     + XOFF;
            const float xg = s_raw[j + 1] + XOFF;
            const float xb = s_raw[j + 2] + XOFF;
            H[n] = fmaf(xr, p1.x - p0.x,
                   fmaf(xg, p1.y - p0.y,
                   fmaf(xb, p1.z - p0.z, -(p1.w - p0.w))));
        }
    }
}

extern "C" void kernel_launch(void* const* d_in, const int* in_sizes, int n_in,
                              void* d_out, int out_size) {
    const float* x  = (const float*)d_in[0];   // rgbs [1, N, 3]
    const float* Wm = (const float*)d_in[1];   // W [2,3]
    // d_in[2] = bias: cancels exactly (h is window-mean-centered).

    const int N = in_sizes[0] / 3;
    const int K = N - WIN;
    float* H = (float*)d_out;

    const int grid = (N + WPB - 1) / WPB;
    pos_fused_kernel<<<grid, BK>>>(x, Wm, H, N, K);
}

// round 7
// speedup vs baseline: 1.3175x; 1.0175x over previous
#include <cuda_runtime.h>

#define WIN   48
#define HALO  47
#define BK    256
#define WPB   624             // outputs per block
#define NBB   14              // beta 48-blocks: betas i in [0, 672)
#define NMB   15              // moment row 48-blocks stored: rows [0, 720)
#define TXR   768             // staged rows (16 blocks; block 15 = scratch)
#define XOFF  0.75f           // centering constant (exact algebra)

__global__ __launch_bounds__(BK, 4)
void pos_kernel(const float* __restrict__ x, const float* __restrict__ Wm,
                float* __restrict__ H, int N, int K) {
    // Local prefix storage: per 48-block, positions 0..47 = exclusive prefix,
    // position 48 = block total.
    __shared__ float4 s_p0[NMB * 49];   // {Sx,Sy,Sz,Mxx}
    __shared__ float4 s_p1[NMB * 49];   // {Myy,Mzz,Mxy,Mxz}
    __shared__ float  s_p2[NMB * 49];   // Myz
    __shared__ float4 s_bp[NBB * 49];   // beta prefix {br,bg,bb,gamma}
    __shared__ float  s_raw[3 * TXR];   // centered x rows (AoS)

    const int t  = threadIdx.x;
    const int sl = t & 15;              // lane within half-warp (segment)
    const int hw = t >> 4;              // half-warp id 0..15
    const int n0 = blockIdx.x * WPB;
    const int kb = n0 - HALO;           // global row of local index 0
    const int g0 = 3 * kb;

    // ---- stage x (centered), coalesced; zero-pad out of range ----
    for (int e = t; e < 3 * TXR; e += BK) {
        const int g = g0 + e;
        s_raw[e] = (g >= 0 && g < 3 * N) ? (x[g] - XOFF) : 0.f;
    }
    __syncthreads();                                             // B1

    const float W00 = Wm[0], W01 = Wm[1], W02 = Wm[2];
    const float W10 = Wm[3], W11 = Wm[4], W12 = Wm[5];
    const float r0 = W00 + W01 + W02;
    const float r1 = W10 + W11 + W12;

    // ================= moment pass: local 48-prefixes =================
    {
        const int rb = 48 * hw + 3 * sl;    // first of this lane's 3 rows
        const float X0 = s_raw[3*rb+0], Y0 = s_raw[3*rb+1], Z0 = s_raw[3*rb+2];
        const float X1 = s_raw[3*rb+3], Y1 = s_raw[3*rb+4], Z1 = s_raw[3*rb+5];
        const float X2 = s_raw[3*rb+6], Y2 = s_raw[3*rb+7], Z2 = s_raw[3*rb+8];

        // chunk totals over the 3 rows, 9 channels
        float v[9];
        v[0] = X0+X1+X2; v[1] = Y0+Y1+Y2; v[2] = Z0+Z1+Z2;
        v[3] = fmaf(X2,X2, fmaf(X1,X1, X0*X0));
        v[4] = fmaf(Y2,Y2, fmaf(Y1,Y1, Y0*Y0));
        v[5] = fmaf(Z2,Z2, fmaf(Z1,Z1, Z0*Z0));
        v[6] = fmaf(X2,Y2, fmaf(X1,Y1, X0*Y0));
        v[7] = fmaf(X2,Z2, fmaf(X1,Z1, X0*Z0));
        v[8] = fmaf(Y2,Z2, fmaf(Y1,Z1, Y0*Z0));

        // segmented (half-warp) inclusive scan, 4 steps
        float p[9];
#pragma unroll
        for (int c = 0; c < 9; ++c) p[c] = v[c];
#pragma unroll
        for (int d = 1; d < 16; d <<= 1) {
#pragma unroll
            for (int c = 0; c < 9; ++c) {
                const float u = __shfl_up_sync(0xffffffffu, p[c], d);
                if (sl >= d) p[c] += u;
            }
        }

        if (hw < NMB) {
            float e[9];
#pragma unroll
            for (int c = 0; c < 9; ++c) e[c] = p[c] - v[c];   // exclusive at chunk start
            const int bp = 49 * hw + 3 * sl;
            s_p0[bp] = make_float4(e[0], e[1], e[2], e[3]);
            s_p1[bp] = make_float4(e[4], e[5], e[6], e[7]);
            s_p2[bp] = e[8];
            e[0]+=X0; e[1]+=Y0; e[2]+=Z0;
            e[3]=fmaf(X0,X0,e[3]); e[4]=fmaf(Y0,Y0,e[4]); e[5]=fmaf(Z0,Z0,e[5]);
            e[6]=fmaf(X0,Y0,e[6]); e[7]=fmaf(X0,Z0,e[7]); e[8]=fmaf(Y0,Z0,e[8]);
            s_p0[bp+1] = make_float4(e[0], e[1], e[2], e[3]);
            s_p1[bp+1] = make_float4(e[4], e[5], e[6], e[7]);
            s_p2[bp+1] = e[8];
            e[0]+=X1; e[1]+=Y1; e[2]+=Z1;
            e[3]=fmaf(X1,X1,e[3]); e[4]=fmaf(Y1,Y1,e[4]); e[5]=fmaf(Z1,Z1,e[5]);
            e[6]=fmaf(X1,Y1,e[6]); e[7]=fmaf(X1,Z1,e[7]); e[8]=fmaf(Y1,Z1,e[8]);
            s_p0[bp+2] = make_float4(e[0], e[1], e[2], e[3]);
            s_p1[bp+2] = make_float4(e[4], e[5], e[6], e[7]);
            s_p2[bp+2] = e[8];
            if (sl == 15) {   // block total at position 48
                e[0]+=X2; e[1]+=Y2; e[2]+=Z2;
                e[3]=fmaf(X2,X2,e[3]); e[4]=fmaf(Y2,Y2,e[4]); e[5]=fmaf(Z2,Z2,e[5]);
                e[6]=fmaf(X2,Y2,e[6]); e[7]=fmaf(X2,Z2,e[7]); e[8]=fmaf(Y2,Z2,e[8]);
                const int bt = 49 * hw + 48;
                s_p0[bt] = make_float4(e[0], e[1], e[2], e[3]);
                s_p1[bt] = make_float4(e[4], e[5], e[6], e[7]);
                s_p2[bt] = e[8];
            }
        }
    }
    __syncthreads();                                             // B2

    // ================= beta pass: 3 betas/lane + local 48-prefix =================
    {
        const int blkL = (hw < NBB) ? hw : (NBB - 1);   // clamped for loads only
        const int o0 = 3 * sl;
        // block totals: uniform across the half-warp (broadcast loads), hoisted
        const float4 T0 = s_p0[49 * blkL + 48];
        const float4 T1 = s_p1[49 * blkL + 48];
        const float  Tz = s_p2[49 * blkL + 48];

        float4 vb[3];
        float v4[4] = {0.f, 0.f, 0.f, 0.f};
#pragma unroll
        for (int r = 0; r < 3; ++r) {
            const int o = o0 + r;
            const float4 A0 = s_p0[49 * blkL + o];
            const float4 A1 = s_p1[49 * blkL + o];
            const float  Az = s_p2[49 * blkL + o];
            const float4 B0 = s_p0[49 * (blkL + 1) + o];
            const float4 B1 = s_p1[49 * (blkL + 1) + o];
            const float  Bz = s_p2[49 * (blkL + 1) + o];

            float4 out = make_float4(0.f, 0.f, 0.f, 0.f);
            const int i = 48 * hw + o;
            const int k = kb + i;
            if (hw < NBB && k >= 0 && k < K) {
                const float Sx  = T0.x - A0.x + B0.x;
                const float Sy  = T0.y - A0.y + B0.y;
                const float Sz  = T0.z - A0.z + B0.z;
                const float Mxx = T0.w - A0.w + B0.w;
                const float Myy = T1.x - A1.x + B1.x;
                const float Mzz = T1.y - A1.y + B1.y;
                const float Mxy = T1.z - A1.z + B1.z;
                const float Mxz = T1.w - A1.w + B1.w;
                const float Myz = Tz   - Az   + Bz;

                const float imr = __fdividef(48.f, Sx + 48.f * XOFF);
                const float img = __fdividef(48.f, Sy + 48.f * XOFF);
                const float imb = __fdividef(48.f, Sz + 48.f * XOFF);
                const float a0r = W00 * imr, a0g = W01 * img, a0b = W02 * imb;
                const float a1r = W10 * imr, a1g = W11 * img, a1b = W12 * imb;
                const float T0s = a0r * Sx + a0g * Sy + a0b * Sz;
                const float T1s = a1r * Sx + a1g * Sy + a1b * Sz;
                const float q0 = a0r * a0r * Mxx + a0g * a0g * Myy + a0b * a0b * Mzz
                               + 2.f * (a0r * a0g * Mxy + a0r * a0b * Mxz + a0g * a0b * Myz)
                               - T0s * T0s * (1.f / 48.f);
                const float q1 = a1r * a1r * Mxx + a1g * a1g * Myy + a1b * a1b * Mzz
                               + 2.f * (a1r * a1g * Mxy + a1r * a1b * Mxz + a1g * a1b * Myz)
                               - T1s * T1s * (1.f / 48.f);
                const float alpha = q0 * rsqrtf(q0 * q1);   // sqrt(q0/q1)
                out.x = fmaf(alpha, W10, W00) * imr;
                out.y = fmaf(alpha, W11, W01) * img;
                out.z = fmaf(alpha, W12, W02) * imb;
                out.w = fmaf(alpha, r1, r0);                // beta . m (exact)
            }
            vb[r] = out;
            v4[0] += out.x; v4[1] += out.y; v4[2] += out.z; v4[3] += out.w;
        }

        // segmented scan of beta chunk totals
        float p4[4];
#pragma unroll
        for (int c = 0; c < 4; ++c) p4[c] = v4[c];
#pragma unroll
        for (int d = 1; d < 16; d <<= 1) {
#pragma unroll
            for (int c = 0; c < 4; ++c) {
                const float u = __shfl_up_sync(0xffffffffu, p4[c], d);
                if (sl >= d) p4[c] += u;
            }
        }

        if (hw < NBB) {
            float e0 = p4[0]-v4[0], e1 = p4[1]-v4[1], e2 = p4[2]-v4[2], e3 = p4[3]-v4[3];
            const int bp = 49 * hw + o0;
            s_bp[bp] = make_float4(e0, e1, e2, e3);
            e0 += vb[0].x; e1 += vb[0].y; e2 += vb[0].z; e3 += vb[0].w;
            s_bp[bp+1] = make_float4(e0, e1, e2, e3);
            e0 += vb[1].x; e1 += vb[1].y; e2 += vb[1].z; e3 += vb[1].w;
            s_bp[bp+2] = make_float4(e0, e1, e2, e3);
            if (sl == 15) {
                e0 += vb[2].x; e1 += vb[2].y; e2 += vb[2].z; e3 += vb[2].w;
                s_bp[49 * hw + 48] = make_float4(e0, e1, e2, e3);
            }
        }
    }
    __syncthreads();                                             // B3

    // ================= output pass =================
#pragma unroll
    for (int c0 = 0; c0 < 3; ++c0) {
        const int m = t + c0 * BK;
        if (m < WPB) {
            const int a = m / 48;
            const int o = m - 48 * a;
            const float4 P48 = s_bp[49 * a + 48];
            const float4 Po  = s_bp[49 * a + o];
            const float4 Q   = s_bp[49 * (a + 1) + o];
            const int n = n0 + m;
            if (n < N) {
                const int j = 3 * (m + HALO);
                const float xr = s_raw[j]     + XOFF;
                const float xg = s_raw[j + 1] + XOFF;
                const float xb = s_raw[j + 2] + XOFF;
                const float Br = P48.x - Po.x + Q.x;
                const float Bg = P48.y - Po.y + Q.y;
                const float Bb = P48.z - Po.z + Q.z;
                const float G  = P48.w - Po.w + Q.w;
                H[n] = fmaf(xr, Br, fmaf(xg, Bg, fmaf(xb, Bb, -G)));
            }
        }
    }
}

extern "C" void kernel_launch(void* const* d_in, const int* in_sizes, int n_in,
                              void* d_out, int out_size) {
    const float* x  = (const float*)d_in[0];   // rgbs [1, N, 3]
    const float* Wm = (const float*)d_in[1];   // W [2,3]
    // d_in[2] = bias: cancels exactly (h is window-mean-centered).

    const int N = in_sizes[0] / 3;
    const int K = N - WIN;
    float* H = (float*)d_out;

    const int grid = (N + WPB - 1) / WPB;
    pos_kernel<<<grid, BK>>>(x, Wm, H, N, K);
}

// round 8
// speedup vs baseline: 1.5685x; 1.1905x over previous
#include <cuda_runtime.h>

#define WIN   48
#define HALO  47
#define BK    256
#define WPB   624             // outputs per block
#define NBB   14              // beta 48-blocks: betas i in [0, 672)
#define NMB   15              // moment 48-blocks stored: rows [0, 720)
#define TXR   768             // staged rows (16 blocks; block 15 = scratch)
#define XOFF  0.75f

// ---- shared layout ----
// [ s_p0 float4*NMB*49 | s_p1 float4*NMB*49 | s_p2 float*NMB*49 ] = 26460 B
//   s_bp (float4*NBB*49 = 10976 B) aliases s_p0 after barrier B3.
// [ s_buf float*2308 ] = 9232 B  (x staged at +3 float shift for alignment)
#define BUF_OFF  ((2 * NMB * 49 * 16 + NMB * 49 * 4 + 15) & ~15)
#define SMEM_TOT (BUF_OFF + 2308 * 4)

__global__ __launch_bounds__(BK, 5)
void pos_kernel(const float* __restrict__ x, const float* __restrict__ Wm,
                float* __restrict__ H, int N, int K) {
    __shared__ __align__(16) char smem[SMEM_TOT];
    float4* s_p0 = (float4*)smem;                      // {Sx,Sy,Sz,Mxx} prefixes
    float4* s_p1 = s_p0 + NMB * 49;                    // {Myy,Mzz,Mxy,Mxz}
    float*  s_p2 = (float*)(s_p1 + NMB * 49);          // Myz
    float4* s_bp = (float4*)smem;                      // beta prefixes (alias s_p0)
    float*  s_buf = (float*)(smem + BUF_OFF);          // centered x; row e at s_buf[3+e]

    const int t  = threadIdx.x;
    const int sl = t & 15;              // lane in half-warp segment
    const int hw = t >> 4;              // half-warp id 0..15
    const int n0 = blockIdx.x * WPB;
    const int kb = n0 - HALO;           // global row of local index 0

    // interior: staging window [3kb-3, 3kb+9229) in-range AND all betas valid AND all n<N
    const bool interior = (kb >= 1) && (kb + 769 <= N) && (kb + NBB * 48 <= K);

    if (interior) {
        // kb = 624*b - 47 => kb ≡ 1 (mod 4) => 3kb-3 ≡ 0 (mod 4): aligned float4 base.
        const float4* x4 = (const float4*)(x + (3 * kb - 3));
        float4* b4 = (float4*)s_buf;
#pragma unroll
        for (int c0 = 0; c0 < 3; ++c0) {
            const int j = t + c0 * BK;
            if (j < 577) {
                float4 v = x4[j];
                v.x -= XOFF; v.y -= XOFF; v.z -= XOFF; v.w -= XOFF;
                b4[j] = v;
            }
        }
    } else {
        const int g0 = 3 * kb;
        for (int e = t; e < 3 * TXR; e += BK) {
            const int g = g0 + e;
            s_buf[3 + e] = (g >= 0 && g < 3 * N) ? (x[g] - XOFF) : 0.f;
        }
    }
    __syncthreads();                                             // B1

    const float W00 = Wm[0], W01 = Wm[1], W02 = Wm[2];
    const float W10 = Wm[3], W11 = Wm[4], W12 = Wm[5];
    const float r0 = W00 + W01 + W02;
    const float r1 = W10 + W11 + W12;

    // ================= moment pass: local 48-block prefixes =================
    {
        const float* rp = s_buf + 3 + 3 * (48 * hw + 3 * sl);
        const float X0 = rp[0], Y0 = rp[1], Z0 = rp[2];
        const float X1 = rp[3], Y1 = rp[4], Z1 = rp[5];
        const float X2 = rp[6], Y2 = rp[7], Z2 = rp[8];

        float v[9];
        v[0] = X0 + X1 + X2; v[1] = Y0 + Y1 + Y2; v[2] = Z0 + Z1 + Z2;
        v[3] = fmaf(X2, X2, fmaf(X1, X1, X0 * X0));
        v[4] = fmaf(Y2, Y2, fmaf(Y1, Y1, Y0 * Y0));
        v[5] = fmaf(Z2, Z2, fmaf(Z1, Z1, Z0 * Z0));
        v[6] = fmaf(X2, Y2, fmaf(X1, Y1, X0 * Y0));
        v[7] = fmaf(X2, Z2, fmaf(X1, Z1, X0 * Z0));
        v[8] = fmaf(Y2, Z2, fmaf(Y1, Z1, Y0 * Z0));

        float p[9];
#pragma unroll
        for (int c = 0; c < 9; ++c) p[c] = v[c];
#pragma unroll
        for (int d = 1; d < 16; d <<= 1) {
#pragma unroll
            for (int c = 0; c < 9; ++c) {
                const float u = __shfl_up_sync(0xffffffffu, p[c], d);
                if (sl >= d) p[c] += u;
            }
        }

        if (hw < NMB) {
            float e[9];
#pragma unroll
            for (int c = 0; c < 9; ++c) e[c] = p[c] - v[c];
            const int bp = 49 * hw + 3 * sl;
            s_p0[bp] = make_float4(e[0], e[1], e[2], e[3]);
            s_p1[bp] = make_float4(e[4], e[5], e[6], e[7]);
            s_p2[bp] = e[8];
            e[0] += X0; e[1] += Y0; e[2] += Z0;
            e[3] = fmaf(X0, X0, e[3]); e[4] = fmaf(Y0, Y0, e[4]); e[5] = fmaf(Z0, Z0, e[5]);
            e[6] = fmaf(X0, Y0, e[6]); e[7] = fmaf(X0, Z0, e[7]); e[8] = fmaf(Y0, Z0, e[8]);
            s_p0[bp + 1] = make_float4(e[0], e[1], e[2], e[3]);
            s_p1[bp + 1] = make_float4(e[4], e[5], e[6], e[7]);
            s_p2[bp + 1] = e[8];
            e[0] += X1; e[1] += Y1; e[2] += Z1;
            e[3] = fmaf(X1, X1, e[3]); e[4] = fmaf(Y1, Y1, e[4]); e[5] = fmaf(Z1, Z1, e[5]);
            e[6] = fmaf(X1, Y1, e[6]); e[7] = fmaf(X1, Z1, e[7]); e[8] = fmaf(Y1, Z1, e[8]);
            s_p0[bp + 2] = make_float4(e[0], e[1], e[2], e[3]);
            s_p1[bp + 2] = make_float4(e[4], e[5], e[6], e[7]);
            s_p2[bp + 2] = e[8];
            if (sl == 15) {   // block total at position 48
                e[0] += X2; e[1] += Y2; e[2] += Z2;
                e[3] = fmaf(X2, X2, e[3]); e[4] = fmaf(Y2, Y2, e[4]); e[5] = fmaf(Z2, Z2, e[5]);
                e[6] = fmaf(X2, Y2, e[6]); e[7] = fmaf(X2, Z2, e[7]); e[8] = fmaf(Y2, Z2, e[8]);
                const int bt = 49 * hw + 48;
                s_p0[bt] = make_float4(e[0], e[1], e[2], e[3]);
                s_p1[bt] = make_float4(e[4], e[5], e[6], e[7]);
                s_p2[bt] = e[8];
            }
        }
    }
    __syncthreads();                                             // B2

    // ========== beta pass: 3 betas/lane, held in regs + segmented scan ==========
    float4 vb[3];
    float e0, e1, e2, e3;   // running beta prefix for this lane's 3 slots
    {
        const int blkL = (hw < NBB) ? hw : (NBB - 1);
        const int o0 = 3 * sl;
        const int lo = (kb < 0) ? -kb : 0;
        const int hi = (K - kb < NBB * 48) ? (K - kb) : (NBB * 48);

        const float4 T0 = s_p0[49 * blkL + 48];
        const float4 T1 = s_p1[49 * blkL + 48];
        const float  Tz = s_p2[49 * blkL + 48];

        float v4[4] = {0.f, 0.f, 0.f, 0.f};
#pragma unroll
        for (int r = 0; r < 3; ++r) {
            const int o = o0 + r;
            const float4 A0 = s_p0[49 * blkL + o];
            const float4 A1 = s_p1[49 * blkL + o];
            const float  Az = s_p2[49 * blkL + o];
            const float4 B0 = s_p0[49 * (blkL + 1) + o];
            const float4 B1 = s_p1[49 * (blkL + 1) + o];
            const float  Bz = s_p2[49 * (blkL + 1) + o];

            float4 out = make_float4(0.f, 0.f, 0.f, 0.f);
            const int i = 48 * hw + o;
            if (i >= lo && i < hi) {
                const float Sx  = T0.x - A0.x + B0.x;
                const float Sy  = T0.y - A0.y + B0.y;
                const float Sz  = T0.z - A0.z + B0.z;
                const float Mxx = T0.w - A0.w + B0.w;
                const float Myy = T1.x - A1.x + B1.x;
                const float Mzz = T1.y - A1.y + B1.y;
                const float Mxy = T1.z - A1.z + B1.z;
                const float Mxz = T1.w - A1.w + B1.w;
                const float Myz = Tz   - Az   + Bz;

                const float imr = __fdividef(48.f, Sx + 48.f * XOFF);
                const float img = __fdividef(48.f, Sy + 48.f * XOFF);
                const float imb = __fdividef(48.f, Sz + 48.f * XOFF);
                const float a0r = W00 * imr, a0g = W01 * img, a0b = W02 * imb;
                const float a1r = W10 * imr, a1g = W11 * img, a1b = W12 * imb;
                const float T0s = a0r * Sx + a0g * Sy + a0b * Sz;
                const float T1s = a1r * Sx + a1g * Sy + a1b * Sz;
                const float q0 = a0r * a0r * Mxx + a0g * a0g * Myy + a0b * a0b * Mzz
                               + 2.f * (a0r * a0g * Mxy + a0r * a0b * Mxz + a0g * a0b * Myz)
                               - T0s * T0s * (1.f / 48.f);
                const float q1 = a1r * a1r * Mxx + a1g * a1g * Myy + a1b * a1b * Mzz
                               + 2.f * (a1r * a1g * Mxy + a1r * a1b * Mxz + a1g * a1b * Myz)
                               - T1s * T1s * (1.f / 48.f);
                const float alpha = q0 * rsqrtf(q0 * q1);   // sqrt(q0/q1)
                out.x = fmaf(alpha, W10, W00) * imr;
                out.y = fmaf(alpha, W11, W01) * img;
                out.z = fmaf(alpha, W12, W02) * imb;
                out.w = fmaf(alpha, r1, r0);                // beta . m (exact)
            }
            vb[r] = out;
            v4[0] += out.x; v4[1] += out.y; v4[2] += out.z; v4[3] += out.w;
        }

        float p4[4];
#pragma unroll
        for (int c = 0; c < 4; ++c) p4[c] = v4[c];
#pragma unroll
        for (int d = 1; d < 16; d <<= 1) {
#pragma unroll
            for (int c = 0; c < 4; ++c) {
                const float u = __shfl_up_sync(0xffffffffu, p4[c], d);
                if (sl >= d) p4[c] += u;
            }
        }
        e0 = p4[0] - v4[0]; e1 = p4[1] - v4[1]; e2 = p4[2] - v4[2]; e3 = p4[3] - v4[3];
    }
    __syncthreads();   // B3: all s_p reads done; s_bp may overwrite s_p0

    if (hw < NBB) {
        const int bp = 49 * hw + 3 * sl;
        s_bp[bp] = make_float4(e0, e1, e2, e3);
        e0 += vb[0].x; e1 += vb[0].y; e2 += vb[0].z; e3 += vb[0].w;
        s_bp[bp + 1] = make_float4(e0, e1, e2, e3);
        e0 += vb[1].x; e1 += vb[1].y; e2 += vb[1].z; e3 += vb[1].w;
        s_bp[bp + 2] = make_float4(e0, e1, e2, e3);
        if (sl == 15) {
            e0 += vb[2].x; e1 += vb[2].y; e2 += vb[2].z; e3 += vb[2].w;
            s_bp[49 * hw + 48] = make_float4(e0, e1, e2, e3);
        }
    }
    __syncthreads();                                             // B4

    // ================= output pass =================
#pragma unroll
    for (int c0 = 0; c0 < 3; ++c0) {
        const int m = t + c0 * BK;
        if (m < WPB) {
            const int a = m / 48;
            const int o = m - 48 * a;
            const float4 P48 = s_bp[49 * a + 48];
            const float4 Po  = s_bp[49 * a + o];
            const float4 Q   = s_bp[49 * (a + 1) + o];
            const int n = n0 + m;
            if (n < N) {
                const float* xp = s_buf + 3 + 3 * (m + HALO);
                const float xr = xp[0] + XOFF;
                const float xg = xp[1] + XOFF;
                const float xb = xp[2] + XOFF;
                const float Br = P48.x - Po.x + Q.x;
                const float Bg = P48.y - Po.y + Q.y;
                const float Bb = P48.z - Po.z + Q.z;
                const float G  = P48.w - Po.w + Q.w;
                H[n] = fmaf(xr, Br, fmaf(xg, Bg, fmaf(xb, Bb, -G)));
            }
        }
    }
}

extern "C" void kernel_launch(void* const* d_in, const int* in_sizes, int n_in,
                              void* d_out, int out_size) {
    const float* x  = (const float*)d_in[0];   // rgbs [1, N, 3]
    const float* Wm = (const float*)d_in[1];   // W [2,3]
    // d_in[2] = bias: cancels exactly (h is window-mean-centered).

    const int N = in_sizes[0] / 3;
    const int K = N - WIN;
    float* H = (float*)d_out;

    const int grid = (N + WPB - 1) / WPB;
    pos_kernel<<<grid, BK>>>(x, Wm, H, N, K);
}